// round 11
// baseline (speedup 1.0000x reference)
#include <cuda_runtime.h>
#include <cstdint>

// ---------------------------------------------------------------------------
// MQNet round 11: packed f32x2 FMA GEMM (Blackwell FFMA2 via PTX fma.rn.f32x2).
//   Each 64-bit lane = independent fma.rn.f32  => every C element keeps the
//   strictly k-ordered fp32 chain of R1/R10 (bitwise-identical output,
//   rel_err must stay exactly 3.496532e-05) at 2x FFMA throughput.
//   R10 data: scalar-FFMA GEMM runs at 31 TF/s = 89% of the 35 TF/s
//   reg-reg FFMA ceiling; FFMA2 raises the ceiling to ~70 TF/s.
// ---------------------------------------------------------------------------

#define NN 8192
#define HH 512
#define H3 1536
#define BS 20
#define BK 16

// ------------------------- device scratch (no mallocs) ---------------------
__device__ float g_xw[NN * HH];
__device__ float g_feats[NN * HH];
__device__ float g_gcn[NN * HH];
__device__ float g_gi[(size_t)NN * H3];
__device__ float g_h[HH];
__device__ float g_gh[H3];
__device__ unsigned long long g_key;
__device__ int g_mask[NN];

// ------------------------- helpers -----------------------------------------
__device__ __forceinline__ unsigned ford(float f) {
    unsigned u = __float_as_uint(f);
    return (u & 0x80000000u) ? ~u : (u | 0x80000000u);
}
__device__ __forceinline__ float forddec(unsigned u) {
    return (u & 0x80000000u) ? __uint_as_float(u & 0x7FFFFFFFu)
                             : __uint_as_float(~u);
}
__device__ __forceinline__ float sigf(float x) {
    return 1.0f / (1.0f + __expf(-x));
}
__device__ __forceinline__ float tanh_f(float x) {
    return 1.0f - 2.0f / (1.0f + __expf(2.0f * x));
}
// packed dual fp32 FMA: d = a*b + d, lanewise (each half = fma.rn.f32)
__device__ __forceinline__ void ffma2(unsigned long long& d,
                                      unsigned long long a,
                                      unsigned long long b) {
    asm volatile("fma.rn.f32x2 %0, %1, %2, %3;"
                 : "=l"(d) : "l"(a), "l"(b), "l"(d));
}

// ------------------------- f32x2 SGEMM (bitwise == R1) ----------------------
// C[M,N] = A[M,K] * op(B) (+bias) (relu).
//   BT=false: B is [K,N]; BT=true: B is [N,K] (use B^T).
// SMEM layouts (innermost padded to 17 to soften store conflicts):
//   sA[k][i][ty] = (v, v)          duplicated A value, m = ty*8 + i
//   sB[k][j][tx] = (B_n, B_{n+1})  n = tx*8 + 2j
// 256 threads: tx = t&15 (n), ty = t>>4 (m); 8x8 microtile as 8x4 f32x2.
template <bool BT, int EPI>  // EPI: 0 none, 1 +bias, 2 +bias & relu
__global__ void __launch_bounds__(256)
sgemm_x2(const float* __restrict__ A, const float* __restrict__ B,
         const float* __restrict__ bias, float* __restrict__ C,
         int M, int N, int K) {
    __shared__ float2 sA[BK][8][17];
    __shared__ float2 sB[BK][4][17];

    const int t = threadIdx.x;
    const int tx = t & 15;
    const int ty = t >> 4;
    const int m0 = blockIdx.y * 128;
    const int n0 = blockIdx.x * 128;

    unsigned long long acc2[8][4];
#pragma unroll
    for (int i = 0; i < 8; i++)
#pragma unroll
        for (int j = 0; j < 4; j++) acc2[i][j] = 0ull;  // (+0.f, +0.f)

    const float* Ab = A + (size_t)m0 * K;

    for (int k0 = 0; k0 < K; k0 += BK) {
        // ---- load A tile (128 x 16), duplicate into float2 ----
#pragma unroll
        for (int i = 0; i < 2; i++) {
            int lin = t + i * 256;           // 0..511
            int r = lin >> 2;                // 0..127
            int kc = (lin & 3) * 4;          // 0,4,8,12
            float4 v = *reinterpret_cast<const float4*>(
                Ab + (size_t)r * K + k0 + kc);
            int ii = r & 7, tt = r >> 3;
            sA[kc + 0][ii][tt] = make_float2(v.x, v.x);
            sA[kc + 1][ii][tt] = make_float2(v.y, v.y);
            sA[kc + 2][ii][tt] = make_float2(v.z, v.z);
            sA[kc + 3][ii][tt] = make_float2(v.w, v.w);
        }
        // ---- load B tile (16 x 128) into paired layout ----
#pragma unroll
        for (int i = 0; i < 2; i++) {
            int lin = t + i * 256;
            if (!BT) {
                int row = lin >> 5;          // k: 0..15
                int c = (lin & 31) * 4;      // n: 0..124
                float4 v = *reinterpret_cast<const float4*>(
                    B + (size_t)(k0 + row) * N + n0 + c);
                float vv[4] = {v.x, v.y, v.z, v.w};
#pragma unroll
                for (int c2 = 0; c2 < 4; c2++) {
                    int n = c + c2;
                    float* p = reinterpret_cast<float*>(
                        &sB[row][(n & 7) >> 1][n >> 3]);
                    p[n & 1] = vv[c2];
                }
            } else {
                int r = lin >> 2;            // n: 0..127
                int kc = (lin & 3) * 4;
                float4 v = *reinterpret_cast<const float4*>(
                    B + (size_t)(n0 + r) * K + k0 + kc);
                float vv[4] = {v.x, v.y, v.z, v.w};
                int jj = (r & 7) >> 1, tt = r >> 3, h = r & 1;
#pragma unroll
                for (int c2 = 0; c2 < 4; c2++) {
                    float* p = reinterpret_cast<float*>(&sB[kc + c2][jj][tt]);
                    p[h] = vv[c2];
                }
            }
        }
        __syncthreads();

        // ---- inner: 12 LDS.64 + 32 FFMA2 per kk ----
#pragma unroll
        for (int kk = 0; kk < BK; kk++) {
            unsigned long long a2[8], b2[4];
#pragma unroll
            for (int i = 0; i < 8; i++)
                a2[i] = *reinterpret_cast<const unsigned long long*>(
                    &sA[kk][i][ty]);
#pragma unroll
            for (int j = 0; j < 4; j++)
                b2[j] = *reinterpret_cast<const unsigned long long*>(
                    &sB[kk][j][tx]);
#pragma unroll
            for (int i = 0; i < 8; i++)
#pragma unroll
                for (int j = 0; j < 4; j++) ffma2(acc2[i][j], a2[i], b2[j]);
        }
        __syncthreads();
    }

    // ---------------- epilogue (identical arithmetic to R1) ------------------
#pragma unroll
    for (int i = 0; i < 8; i++) {
        int m = m0 + ty * 8 + i;
#pragma unroll
        for (int j = 0; j < 4; j++) {
            int col = n0 + tx * 8 + 2 * j;
            float v0 = __uint_as_float((unsigned)(acc2[i][j] & 0xFFFFFFFFull));
            float v1 = __uint_as_float((unsigned)(acc2[i][j] >> 32));
            if (EPI >= 1) { v0 += bias[col]; v1 += bias[col + 1]; }
            if (EPI == 2) { v0 = fmaxf(v0, 0.f); v1 = fmaxf(v1, 0.f); }
            *reinterpret_cast<float2*>(C + (size_t)m * N + col) =
                make_float2(v0, v1);
        }
    }
}

// ------------------------- init: mask=1, key=0 ------------------------------
__global__ void init_kernel() {
    int i = blockIdx.x * blockDim.x + threadIdx.x;
    if (i < NN) g_mask[i] = 1;
    if (i == 0) g_key = 0ull;
}

// ------------------------- step-0 GEMV + argmax (verbatim R1) ---------------
__global__ void __launch_bounds__(256)
gemv_argmax_kernel(const float* __restrict__ w, const float* __restrict__ b) {
    __shared__ float sw[HH];
    __shared__ unsigned long long skey[8];
    int t = threadIdx.x;
    for (int j = t; j < HH; j += 256) sw[j] = w[j];
    __syncthreads();

    int wid = t >> 5, lane = t & 31;
    int i = blockIdx.x * 8 + wid;
    const float* row = g_gcn + (size_t)i * HH;
    float acc = 0.f;
#pragma unroll 4
    for (int jj = 0; jj < 16; jj++) {
        int j = lane + jj * 32;
        acc += row[j] * sw[j];
    }
#pragma unroll
    for (int o = 16; o; o >>= 1) acc += __shfl_down_sync(0xffffffffu, acc, o);
    if (lane == 0) {
        float v = acc + b[0];
        skey[wid] = ((unsigned long long)ford(v) << 32) |
                    (0xFFFFFFFFu - (unsigned)i);
    }
    __syncthreads();
    if (t == 0) {
        unsigned long long best = skey[0];
#pragma unroll
        for (int w2 = 1; w2 < 8; w2++) best = best > skey[w2] ? best : skey[w2];
        atomicMax(&g_key, best);
    }
}

// ------------------------- gh = h @ W_hh^T + b_hh (verbatim R1) -------------
__global__ void __launch_bounds__(256)
gh_kernel(const float* __restrict__ Whh, const float* __restrict__ bhh) {
    __shared__ float sh[HH];
    int t = threadIdx.x;
    for (int j = t; j < HH; j += 256) sh[j] = g_h[j];
    __syncthreads();
    int wid = t >> 5, lane = t & 31;
    int o = blockIdx.x * 8 + wid;
    const float* wr = Whh + (size_t)o * HH;
    float acc = 0.f;
#pragma unroll 4
    for (int jj = 0; jj < 16; jj++) {
        int j = lane + jj * 32;
        acc += wr[j] * sh[j];
    }
#pragma unroll
    for (int off = 16; off; off >>= 1)
        acc += __shfl_down_sync(0xffffffffu, acc, off);
    if (lane == 0) g_gh[o] = acc + bhh[o];
}

// ------------------------- GRU elementwise + vals + argmax (verbatim R1) ----
__global__ void __launch_bounds__(256)
gru_vals_kernel(const float* __restrict__ w2, const float* __restrict__ b2) {
    __shared__ float sgh[H3];
    __shared__ float sh[HH];
    __shared__ float sw[HH];
    __shared__ unsigned long long skey[8];
    int t = threadIdx.x;
    for (int j = t; j < H3; j += 256) sgh[j] = g_gh[j];
    for (int j = t; j < HH; j += 256) {
        sh[j] = g_h[j];
        sw[j] = w2[j];
    }
    __syncthreads();

    int wid = t >> 5, lane = t & 31;
    int i = blockIdx.x * 8 + wid;
    unsigned long long key = 0ull;
    if (g_mask[i]) {
        const float* gi = g_gi + (size_t)i * H3;
        float acc = 0.f;
#pragma unroll 4
        for (int jj = 0; jj < 16; jj++) {
            int j = lane + jj * 32;
            float r = sigf(gi[j] + sgh[j]);
            float z = sigf(gi[j + 512] + sgh[j + 512]);
            float ng = tanh_f(gi[j + 1024] + r * sgh[j + 1024]);
            float rnn = (1.f - z) * ng + z * sh[j];
            acc += sw[j] * rnn;
        }
#pragma unroll
        for (int o = 16; o; o >>= 1) acc += __shfl_down_sync(0xffffffffu, acc, o);
        if (lane == 0) {
            float v = acc + b2[0];
            key = ((unsigned long long)ford(v) << 32) |
                  (0xFFFFFFFFu - (unsigned)i);
        }
    }
    if (lane == 0) skey[wid] = key;
    __syncthreads();
    if (t == 0) {
        unsigned long long best = skey[0];
#pragma unroll
        for (int w = 1; w < 8; w++) best = best > skey[w] ? best : skey[w];
        atomicMax(&g_key, best);
    }
}

// ------------------------- select (verbatim R1) -----------------------------
__global__ void __launch_bounds__(512)
select_kernel(float* __restrict__ out, int step, int first) {
    __shared__ int sidx;
    int t = threadIdx.x;
    if (t == 0) {
        unsigned long long key = g_key;
        int idx = (int)(0xFFFFFFFFu - (unsigned)(key & 0xFFFFFFFFull));
        float v = forddec((unsigned)(key >> 32));
        out[step] = (float)idx;
        out[BS + step] = v;
        g_mask[idx] = 0;
        g_key = 0ull;
        sidx = idx;
    }
    __syncthreads();
    int idx = sidx;
    int j = t;
    if (first) {
        g_h[j] = g_gcn[(size_t)idx * HH + j];
    } else {
        const float* gi = g_gi + (size_t)idx * H3;
        float r = sigf(gi[j] + g_gh[j]);
        float z = sigf(gi[j + 512] + g_gh[j + 512]);
        float ng = tanh_f(gi[j + 1024] + r * g_gh[j + 1024]);
        g_h[j] = (1.f - z) * ng + z * g_h[j];
    }
}

// ------------------------- launch ------------------------------------------
extern "C" void kernel_launch(void* const* d_in, const int* in_sizes, int n_in,
                              void* d_out, int out_size) {
    (void)in_sizes; (void)n_in; (void)out_size;
    const float* state  = (const float*)d_in[0];
    const float* adj    = (const float*)d_in[1];
    const float* W1     = (const float*)d_in[3];
    const float* b1     = (const float*)d_in[4];
    const float* W2     = (const float*)d_in[5];
    const float* b2     = (const float*)d_in[6];
    const float* w_out1 = (const float*)d_in[7];
    const float* b_out1 = (const float*)d_in[8];
    const float* w_out2 = (const float*)d_in[9];
    const float* b_out2 = (const float*)d_in[10];
    const float* W_ih   = (const float*)d_in[11];
    const float* W_hh   = (const float*)d_in[12];
    const float* b_ih   = (const float*)d_in[13];
    const float* b_hh   = (const float*)d_in[14];
    float* out = (float*)d_out;

    float *xw, *feats, *gcn, *gi;
    cudaGetSymbolAddress((void**)&xw, g_xw);
    cudaGetSymbolAddress((void**)&feats, g_feats);
    cudaGetSymbolAddress((void**)&gcn, g_gcn);
    cudaGetSymbolAddress((void**)&gi, g_gi);

    dim3 blk(256);

    init_kernel<<<(NN + 255) / 256, 256>>>();

    // G1: XW = state @ W1
    sgemm_x2<false, 0><<<dim3(HH / 128, NN / 128), blk>>>(
        state, W1, nullptr, xw, NN, HH, HH);
    // G2: feats = relu(adj @ XW + b1)
    sgemm_x2<false, 2><<<dim3(HH / 128, NN / 128), blk>>>(
        adj, xw, b1, feats, NN, HH, NN);
    // G3: XW = feats @ W2
    sgemm_x2<false, 0><<<dim3(HH / 128, NN / 128), blk>>>(
        feats, W2, nullptr, xw, NN, HH, HH);
    // G4: gcn = relu(adj @ XW + b2)
    sgemm_x2<false, 2><<<dim3(HH / 128, NN / 128), blk>>>(
        adj, xw, b2, gcn, NN, HH, NN);
    // G5: gi = gcn @ W_ih^T + b_ih
    sgemm_x2<true, 1><<<dim3(H3 / 128, NN / 128), blk>>>(
        gcn, W_ih, b_ih, gi, NN, H3, HH);

    // step 0
    gemv_argmax_kernel<<<NN / 8, blk>>>(w_out1, b_out1);
    select_kernel<<<1, 512>>>(out, 0, 1);

    // steps 1..19
    for (int t = 1; t < BS; t++) {
        gh_kernel<<<H3 / 8, blk>>>(W_hh, b_hh);
        gru_vals_kernel<<<NN / 8, blk>>>(w_out2, b_out2);
        select_kernel<<<1, 512>>>(out, t, 0);
    }
}

// round 13
// speedup vs baseline: 1.2191x; 1.2191x over previous
#include <cuda_runtime.h>
#include <cstdint>

// ---------------------------------------------------------------------------
// MQNet round 13: FFMA2 GEMM, attempt 2 fixed (R12 had an inline-asm ICE:
//   template referenced %3 with a "+l" 3-operand list). 4-operand form now.
//   - R1's exact SMEM layouts + load phase (bitwise-proven)
//   - B columns remapped to n = j*16 + tx -> conflict-free scalar LDS
//   - register packing (mov.b64) feeds 32 fma.rn.f32x2 per kk
//   Per-element strict k-order retained => rel_err must be 3.496532e-05.
// ---------------------------------------------------------------------------

#define NN 8192
#define HH 512
#define H3 1536
#define BS 20
#define BK 16

// ------------------------- device scratch (no mallocs) ---------------------
__device__ float g_xw[NN * HH];
__device__ float g_feats[NN * HH];
__device__ float g_gcn[NN * HH];
__device__ float g_gi[(size_t)NN * H3];
__device__ float g_h[HH];
__device__ float g_gh[H3];
__device__ unsigned long long g_key;
__device__ int g_mask[NN];

// ------------------------- helpers -----------------------------------------
__device__ __forceinline__ unsigned ford(float f) {
    unsigned u = __float_as_uint(f);
    return (u & 0x80000000u) ? ~u : (u | 0x80000000u);
}
__device__ __forceinline__ float forddec(unsigned u) {
    return (u & 0x80000000u) ? __uint_as_float(u & 0x7FFFFFFFu)
                             : __uint_as_float(~u);
}
__device__ __forceinline__ float sigf(float x) {
    return 1.0f / (1.0f + __expf(-x));
}
__device__ __forceinline__ float tanh_f(float x) {
    return 1.0f - 2.0f / (1.0f + __expf(2.0f * x));
}
__device__ __forceinline__ unsigned long long pack2(float lo, float hi) {
    unsigned long long r;
    asm("mov.b64 %0, {%1, %2};" : "=l"(r) : "f"(lo), "f"(hi));
    return r;
}
__device__ __forceinline__ void unpack2(unsigned long long v, float& lo,
                                        float& hi) {
    asm("mov.b64 {%0, %1}, %2;" : "=f"(lo), "=f"(hi) : "l"(v));
}
// packed dual fp32 FMA: d = a*b + d, each 32-bit lane an exact fma.rn.f32
// (4-operand form: %3 = input copy of d; R11 proved this form compiles+runs)
__device__ __forceinline__ void ffma2(unsigned long long& d,
                                      unsigned long long a,
                                      unsigned long long b) {
    asm volatile("fma.rn.f32x2 %0, %1, %2, %3;"
                 : "=l"(d) : "l"(a), "l"(b), "l"(d));
}

// ------------------------- FFMA2 SGEMM (bitwise == R1) ----------------------
// C[M,N] = A[M,K] * op(B) (+bias) (relu).
//   BT=false: B is [K,N]; BT=true: B is [N,K] (use B^T).
// SMEM layout identical to R1. Thread (tx=t&15, ty=t>>4) computes rows
// m0+ty*8+{0..7} and columns n0 + jj*16 + tx for jj=0..7 (remapped so the
// 16 tx hit consecutive banks -> conflict-free LDS).
template <bool BT, int EPI>  // EPI: 0 none, 1 +bias, 2 +bias & relu
__global__ void __launch_bounds__(256)
sgemm_p2(const float* __restrict__ A, const float* __restrict__ B,
         const float* __restrict__ bias, float* __restrict__ C,
         int M, int N, int K) {
    __shared__ float As[BK][128];
    __shared__ float Bs[BK][128];

    const int t = threadIdx.x;
    const int tx = t & 15;
    const int ty = t >> 4;
    const int m0 = blockIdx.y * 128;
    const int n0 = blockIdx.x * 128;

    unsigned long long acc2[8][4];
#pragma unroll
    for (int i = 0; i < 8; i++)
#pragma unroll
        for (int j = 0; j < 4; j++) acc2[i][j] = 0ull;  // (+0.f, +0.f)

    const float* Ab = A + (size_t)m0 * K;

    for (int k0 = 0; k0 < K; k0 += BK) {
        // ---- load phase: verbatim R1 ----
#pragma unroll
        for (int i = 0; i < 2; i++) {
            int lin = t + i * 256;
            int row = lin >> 2;
            int kc = (lin & 3) * 4;
            float4 v = *reinterpret_cast<const float4*>(
                Ab + (size_t)row * K + k0 + kc);
            As[kc + 0][row] = v.x;
            As[kc + 1][row] = v.y;
            As[kc + 2][row] = v.z;
            As[kc + 3][row] = v.w;
        }
#pragma unroll
        for (int i = 0; i < 2; i++) {
            int lin = t + i * 256;
            if (!BT) {
                int row = lin >> 5;
                int c = (lin & 31) * 4;
                float4 v = *reinterpret_cast<const float4*>(
                    B + (size_t)(k0 + row) * N + n0 + c);
                *reinterpret_cast<float4*>(&Bs[row][c]) = v;
            } else {
                int row = lin >> 2;
                int kc = (lin & 3) * 4;
                float4 v = *reinterpret_cast<const float4*>(
                    B + (size_t)(n0 + row) * K + k0 + kc);
                Bs[kc + 0][row] = v.x;
                Bs[kc + 1][row] = v.y;
                Bs[kc + 2][row] = v.z;
                Bs[kc + 3][row] = v.w;
            }
        }
        __syncthreads();

        // ---- inner loop: 16 conflict-free LDS.32 + 12 packs + 32 FFMA2 ----
#pragma unroll
        for (int kk = 0; kk < BK; kk++) {
            float ra[8], rb[8];
#pragma unroll
            for (int i = 0; i < 8; i++) ra[i] = As[kk][ty * 8 + i];
#pragma unroll
            for (int j = 0; j < 8; j++) rb[j] = Bs[kk][j * 16 + tx];
            unsigned long long a2[8], b2[4];
#pragma unroll
            for (int i = 0; i < 8; i++) a2[i] = pack2(ra[i], ra[i]);
#pragma unroll
            for (int j = 0; j < 4; j++)
                b2[j] = pack2(rb[2 * j], rb[2 * j + 1]);
#pragma unroll
            for (int i = 0; i < 8; i++)
#pragma unroll
                for (int j = 0; j < 4; j++) ffma2(acc2[i][j], a2[i], b2[j]);
        }
        __syncthreads();
    }

    // ---------------- epilogue (same per-element arithmetic as R1) ----------
#pragma unroll
    for (int i = 0; i < 8; i++) {
        int m = m0 + ty * 8 + i;
#pragma unroll
        for (int j = 0; j < 4; j++) {
            float v0, v1;
            unpack2(acc2[i][j], v0, v1);
            int nlo = n0 + (2 * j) * 16 + tx;
            int nhi = n0 + (2 * j + 1) * 16 + tx;
            if (EPI >= 1) { v0 += bias[nlo]; v1 += bias[nhi]; }
            if (EPI == 2) { v0 = fmaxf(v0, 0.f); v1 = fmaxf(v1, 0.f); }
            C[(size_t)m * N + nlo] = v0;
            C[(size_t)m * N + nhi] = v1;
        }
    }
}

// ------------------------- init: mask=1, key=0 ------------------------------
__global__ void init_kernel() {
    int i = blockIdx.x * blockDim.x + threadIdx.x;
    if (i < NN) g_mask[i] = 1;
    if (i == 0) g_key = 0ull;
}

// ------------------------- step-0 GEMV + argmax (verbatim R1) ---------------
__global__ void __launch_bounds__(256)
gemv_argmax_kernel(const float* __restrict__ w, const float* __restrict__ b) {
    __shared__ float sw[HH];
    __shared__ unsigned long long skey[8];
    int t = threadIdx.x;
    for (int j = t; j < HH; j += 256) sw[j] = w[j];
    __syncthreads();

    int wid = t >> 5, lane = t & 31;
    int i = blockIdx.x * 8 + wid;
    const float* row = g_gcn + (size_t)i * HH;
    float acc = 0.f;
#pragma unroll 4
    for (int jj = 0; jj < 16; jj++) {
        int j = lane + jj * 32;
        acc += row[j] * sw[j];
    }
#pragma unroll
    for (int o = 16; o; o >>= 1) acc += __shfl_down_sync(0xffffffffu, acc, o);
    if (lane == 0) {
        float v = acc + b[0];
        skey[wid] = ((unsigned long long)ford(v) << 32) |
                    (0xFFFFFFFFu - (unsigned)i);
    }
    __syncthreads();
    if (t == 0) {
        unsigned long long best = skey[0];
#pragma unroll
        for (int w2 = 1; w2 < 8; w2++) best = best > skey[w2] ? best : skey[w2];
        atomicMax(&g_key, best);
    }
}

// ------------------------- gh = h @ W_hh^T + b_hh (verbatim R1) -------------
__global__ void __launch_bounds__(256)
gh_kernel(const float* __restrict__ Whh, const float* __restrict__ bhh) {
    __shared__ float sh[HH];
    int t = threadIdx.x;
    for (int j = t; j < HH; j += 256) sh[j] = g_h[j];
    __syncthreads();
    int wid = t >> 5, lane = t & 31;
    int o = blockIdx.x * 8 + wid;
    const float* wr = Whh + (size_t)o * HH;
    float acc = 0.f;
#pragma unroll 4
    for (int jj = 0; jj < 16; jj++) {
        int j = lane + jj * 32;
        acc += wr[j] * sh[j];
    }
#pragma unroll
    for (int off = 16; off; off >>= 1)
        acc += __shfl_down_sync(0xffffffffu, acc, off);
    if (lane == 0) g_gh[o] = acc + bhh[o];
}

// ------------------------- GRU elementwise + vals + argmax (verbatim R1) ----
__global__ void __launch_bounds__(256)
gru_vals_kernel(const float* __restrict__ w2, const float* __restrict__ b2) {
    __shared__ float sgh[H3];
    __shared__ float sh[HH];
    __shared__ float sw[HH];
    __shared__ unsigned long long skey[8];
    int t = threadIdx.x;
    for (int j = t; j < H3; j += 256) sgh[j] = g_gh[j];
    for (int j = t; j < HH; j += 256) {
        sh[j] = g_h[j];
        sw[j] = w2[j];
    }
    __syncthreads();

    int wid = t >> 5, lane = t & 31;
    int i = blockIdx.x * 8 + wid;
    unsigned long long key = 0ull;
    if (g_mask[i]) {
        const float* gi = g_gi + (size_t)i * H3;
        float acc = 0.f;
#pragma unroll 4
        for (int jj = 0; jj < 16; jj++) {
            int j = lane + jj * 32;
            float r = sigf(gi[j] + sgh[j]);
            float z = sigf(gi[j + 512] + sgh[j + 512]);
            float ng = tanh_f(gi[j + 1024] + r * sgh[j + 1024]);
            float rnn = (1.f - z) * ng + z * sh[j];
            acc += sw[j] * rnn;
        }
#pragma unroll
        for (int o = 16; o; o >>= 1) acc += __shfl_down_sync(0xffffffffu, acc, o);
        if (lane == 0) {
            float v = acc + b2[0];
            key = ((unsigned long long)ford(v) << 32) |
                  (0xFFFFFFFFu - (unsigned)i);
        }
    }
    if (lane == 0) skey[wid] = key;
    __syncthreads();
    if (t == 0) {
        unsigned long long best = skey[0];
#pragma unroll
        for (int w = 1; w < 8; w++) best = best > skey[w] ? best : skey[w];
        atomicMax(&g_key, best);
    }
}

// ------------------------- select (verbatim R1) -----------------------------
__global__ void __launch_bounds__(512)
select_kernel(float* __restrict__ out, int step, int first) {
    __shared__ int sidx;
    int t = threadIdx.x;
    if (t == 0) {
        unsigned long long key = g_key;
        int idx = (int)(0xFFFFFFFFu - (unsigned)(key & 0xFFFFFFFFull));
        float v = forddec((unsigned)(key >> 32));
        out[step] = (float)idx;
        out[BS + step] = v;
        g_mask[idx] = 0;
        g_key = 0ull;
        sidx = idx;
    }
    __syncthreads();
    int idx = sidx;
    int j = t;
    if (first) {
        g_h[j] = g_gcn[(size_t)idx * HH + j];
    } else {
        const float* gi = g_gi + (size_t)idx * H3;
        float r = sigf(gi[j] + g_gh[j]);
        float z = sigf(gi[j + 512] + g_gh[j + 512]);
        float ng = tanh_f(gi[j + 1024] + r * g_gh[j + 1024]);
        g_h[j] = (1.f - z) * ng + z * g_h[j];
    }
}

// ------------------------- launch ------------------------------------------
extern "C" void kernel_launch(void* const* d_in, const int* in_sizes, int n_in,
                              void* d_out, int out_size) {
    (void)in_sizes; (void)n_in; (void)out_size;
    const float* state  = (const float*)d_in[0];
    const float* adj    = (const float*)d_in[1];
    const float* W1     = (const float*)d_in[3];
    const float* b1     = (const float*)d_in[4];
    const float* W2     = (const float*)d_in[5];
    const float* b2     = (const float*)d_in[6];
    const float* w_out1 = (const float*)d_in[7];
    const float* b_out1 = (const float*)d_in[8];
    const float* w_out2 = (const float*)d_in[9];
    const float* b_out2 = (const float*)d_in[10];
    const float* W_ih   = (const float*)d_in[11];
    const float* W_hh   = (const float*)d_in[12];
    const float* b_ih   = (const float*)d_in[13];
    const float* b_hh   = (const float*)d_in[14];
    float* out = (float*)d_out;

    float *xw, *feats, *gcn, *gi;
    cudaGetSymbolAddress((void**)&xw, g_xw);
    cudaGetSymbolAddress((void**)&feats, g_feats);
    cudaGetSymbolAddress((void**)&gcn, g_gcn);
    cudaGetSymbolAddress((void**)&gi, g_gi);

    dim3 blk(256);

    init_kernel<<<(NN + 255) / 256, 256>>>();

    // G1: XW = state @ W1
    sgemm_p2<false, 0><<<dim3(HH / 128, NN / 128), blk>>>(
        state, W1, nullptr, xw, NN, HH, HH);
    // G2: feats = relu(adj @ XW + b1)
    sgemm_p2<false, 2><<<dim3(HH / 128, NN / 128), blk>>>(
        adj, xw, b1, feats, NN, HH, NN);
    // G3: XW = feats @ W2
    sgemm_p2<false, 0><<<dim3(HH / 128, NN / 128), blk>>>(
        feats, W2, nullptr, xw, NN, HH, HH);
    // G4: gcn = relu(adj @ XW + b2)
    sgemm_p2<false, 2><<<dim3(HH / 128, NN / 128), blk>>>(
        adj, xw, b2, gcn, NN, HH, NN);
    // G5: gi = gcn @ W_ih^T + b_ih
    sgemm_p2<true, 1><<<dim3(H3 / 128, NN / 128), blk>>>(
        gcn, W_ih, b_ih, gi, NN, H3, HH);

    // step 0
    gemv_argmax_kernel<<<NN / 8, blk>>>(w_out1, b_out1);
    select_kernel<<<1, 512>>>(out, 0, 1);

    // steps 1..19
    for (int t = 1; t < BS; t++) {
        gh_kernel<<<H3 / 8, blk>>>(W_hh, b_hh);
        gru_vals_kernel<<<NN / 8, blk>>>(w_out2, b_out2);
        select_kernel<<<1, 512>>>(out, t, 0);
    }
}